// round 1
// baseline (speedup 1.0000x reference)
#include <cuda_runtime.h>

// Problem constants (fixed by the reference setup)
#define TOKENS 2048   // B*T = 2*1024
#define DDIM   1024   // D
#define PDIM   32     // pattern_dim
#define NPAT   256    // n_patterns
#define TOPK   4
#define NT     256    // threads per block

__device__ __forceinline__ float my_silu(float z) {
    return z / (1.0f + __expf(-z));
}

__global__ __launch_bounds__(NT, 4)
void moe_token_kernel(const float* __restrict__ x,     // [2048,1024]
                      const float* __restrict__ hw,    // [32,1024]
                      const float* __restrict__ keys,  // [256,32]
                      const float* __restrict__ vd,    // [256,1024,32]
                      const float* __restrict__ vu,    // [256,32,1024]
                      const float* __restrict__ scale, // [1]
                      float* __restrict__ out)         // [2048,1024]
{
    __shared__ float sx[DDIM];          // token's x
    __shared__ float sh[PDIM];          // h = x @ hw^T
    __shared__ float ssim[NPAT];        // similarities
    __shared__ float accP[32][32];      // partial proj reduction [d-group][p]
    __shared__ float sproj[PDIM];       // silu(x @ Vd)
    __shared__ float swv[TOPK];         // top-k values -> softmax weights
    __shared__ int   sidxk[TOPK];       // top-k expert indices
    __shared__ float rval[NT / 32];     // per-warp argmax value
    __shared__ int   ridx[NT / 32];     // per-warp argmax index

    const int tok  = blockIdx.x;
    const int t    = threadIdx.x;
    const int lane = t & 31;
    const int warp = t >> 5;

    // ---- load x into smem (vectorized) ----
    const float* xr = x + (size_t)tok * DDIM;
    for (int i = t; i < DDIM / 4; i += NT)
        ((float4*)sx)[i] = ((const float4*)xr)[i];
    __syncthreads();

    // ---- h[p] = sum_d x[d] * hw[p][d] : 8 warps, 4 pattern-dims each ----
    #pragma unroll
    for (int pp = 0; pp < 4; pp++) {
        const int p = warp + pp * 8;
        const float* wr = hw + (size_t)p * DDIM;
        float acc = 0.0f;
        for (int d = lane; d < DDIM; d += 32)
            acc += sx[d] * wr[d];
        #pragma unroll
        for (int o = 16; o; o >>= 1)
            acc += __shfl_xor_sync(0xFFFFFFFFu, acc, o);
        if (lane == 0) sh[p] = acc;
    }
    __syncthreads();

    // ---- sim[n] = sum_p h[p] * keys[n][p], one n per thread ----
    {
        const float* kr = keys + (size_t)t * PDIM;
        float acc = 0.0f;
        #pragma unroll
        for (int p = 0; p < PDIM; p++)
            acc += sh[p] * kr[p];
        ssim[t] = acc;
    }
    __syncthreads();

    // ---- top-4 via 4 deterministic argmax passes (tie-break: lower index) ----
    for (int k = 0; k < TOPK; k++) {
        float v = ssim[t];
        int   id = t;
        #pragma unroll
        for (int o = 16; o; o >>= 1) {
            float ov = __shfl_xor_sync(0xFFFFFFFFu, v, o);
            int   oi = __shfl_xor_sync(0xFFFFFFFFu, id, o);
            if (ov > v || (ov == v && oi < id)) { v = ov; id = oi; }
        }
        if (lane == 0) { rval[warp] = v; ridx[warp] = id; }
        __syncthreads();
        if (t == 0) {
            float bv = rval[0]; int bi = ridx[0];
            #pragma unroll
            for (int w = 1; w < NT / 32; w++) {
                if (rval[w] > bv || (rval[w] == bv && ridx[w] < bi)) {
                    bv = rval[w]; bi = ridx[w];
                }
            }
            swv[k] = bv; sidxk[k] = bi;
            ssim[bi] = -1e30f;  // exclude for next pass
        }
        __syncthreads();
    }

    // ---- softmax over the 4 top values ----
    if (t == 0) {
        float m = swv[0];
        #pragma unroll
        for (int k = 1; k < TOPK; k++) m = fmaxf(m, swv[k]);
        float e[TOPK], s = 0.0f;
        #pragma unroll
        for (int k = 0; k < TOPK; k++) { e[k] = __expf(swv[k] - m); s += e[k]; }
        const float inv = 1.0f / s;
        #pragma unroll
        for (int k = 0; k < TOPK; k++) swv[k] = e[k] * inv;
    }
    __syncthreads();

    // ---- main loop over the 4 selected experts ----
    // Each thread owns 4 consecutive output dims: d = 4*t .. 4*t+3
    float4 oacc = make_float4(0.f, 0.f, 0.f, 0.f);

    for (int k = 0; k < TOPK; k++) {
        const int   e  = sidxk[k];
        const float wk = swv[k];

        // proj[p] = sum_d x[d] * Vd[e][d][p]
        // thread layout: pg = t&7 covers p in [4*pg, 4*pg+4), d-row = t>>3 (+32 per iter)
        const float* vdr = vd + (size_t)e * DDIM * PDIM;
        const int pg = t & 7;
        const int dr = t >> 3;
        float4 pa = make_float4(0.f, 0.f, 0.f, 0.f);
        for (int d = dr; d < DDIM; d += 32) {
            const float  xv = sx[d];
            const float4 v  = ((const float4*)(vdr + (size_t)d * PDIM))[pg];
            pa.x += xv * v.x; pa.y += xv * v.y; pa.z += xv * v.z; pa.w += xv * v.w;
        }
        ((float4*)accP[dr])[pg] = pa;
        __syncthreads();

        // reduce 32 d-groups -> proj[p], then silu
        if (t < PDIM) {
            float z = 0.0f;
            #pragma unroll
            for (int r = 0; r < 32; r++) z += accP[r][t];
            sproj[t] = my_silu(z);
        }
        __syncthreads();

        // o[d] = sum_p proj[p] * Vu[e][p][d], accumulate weighted
        const float* vur = vu + (size_t)e * PDIM * DDIM;
        float4 oa = make_float4(0.f, 0.f, 0.f, 0.f);
        #pragma unroll
        for (int p = 0; p < PDIM; p++) {
            const float  pj = sproj[p];
            const float4 v  = ((const float4*)(vur + (size_t)p * DDIM))[t];
            oa.x += pj * v.x; oa.y += pj * v.y; oa.z += pj * v.z; oa.w += pj * v.w;
        }
        oacc.x += wk * oa.x; oacc.y += wk * oa.y;
        oacc.z += wk * oa.z; oacc.w += wk * oa.w;
        // NOTE: no sync needed here; next iteration syncs after accP store
        // before anyone rewrites sproj.
    }

    // ---- out = x + scale * acc ----
    const float  sc = scale[0];
    const float4 xv = ((const float4*)sx)[t];
    float4 o;
    o.x = xv.x + sc * oacc.x;
    o.y = xv.y + sc * oacc.y;
    o.z = xv.z + sc * oacc.z;
    o.w = xv.w + sc * oacc.w;
    ((float4*)(out + (size_t)tok * DDIM))[t] = o;
}

extern "C" void kernel_launch(void* const* d_in, const int* in_sizes, int n_in,
                              void* d_out, int out_size) {
    const float* x     = (const float*)d_in[0];
    const float* hw    = (const float*)d_in[1];
    const float* keys  = (const float*)d_in[2];
    const float* vd    = (const float*)d_in[3];
    const float* vu    = (const float*)d_in[4];
    const float* scale = (const float*)d_in[5];
    float* out = (float*)d_out;

    moe_token_kernel<<<TOKENS, NT>>>(x, hw, keys, vd, vu, scale, out);
}